// round 1
// baseline (speedup 1.0000x reference)
#include <cuda_runtime.h>
#include <math.h>

#define EPSF 1e-7f
#define POS_THR 0.5f
#define NEG_THR 0.4f
#define ALPHA_F 0.25f

#define MAXN 32
#define MAXP 100

// Scratch (no allocation allowed)
__device__ double g_sums[3];              // score, cls, bbox accumulators
__device__ int    g_poscnt[MAXN];         // per-batch positive counts
__device__ int    g_gtbest[MAXN * MAXP];  // best anchor idx per GT if lowq, else -1

__global__ void init_kernel() {
    int t = threadIdx.x;
    if (t < 3) g_sums[t] = 0.0;
    if (t < MAXN) g_poscnt[t] = 0;
}

// One block per (gt p, batch n): find first-argmax anchor for this GT.
__global__ void gt_best_kernel(const float* __restrict__ bbox_true,
                               const float4* __restrict__ anchors,
                               int N, int P, int A) {
    int p = blockIdx.x, n = blockIdx.y;
    const float4 g = reinterpret_cast<const float4*>(bbox_true)[n * P + p];
    bool valid = (g.x > 0.f) || (g.y > 0.f) || (g.z > 0.f) || (g.w > 0.f);
    if (!valid) {
        if (threadIdx.x == 0) g_gtbest[n * P + p] = -1;
        return;
    }
    float areab = (g.z - g.x) * (g.w - g.y);
    float best = -1.0f;
    int bidx = 0x7fffffff;
    for (int a = threadIdx.x; a < A; a += blockDim.x) {
        float4 an = anchors[a];
        float iw = fmaxf(fminf(an.z, g.z) - fmaxf(an.x, g.x), 0.f);
        float ih = fmaxf(fminf(an.w, g.w) - fmaxf(an.y, g.y), 0.f);
        float inter = iw * ih;
        float areaa = (an.z - an.x) * (an.w - an.y);
        float iou = inter / (areaa + areab - inter + EPSF);
        if (iou > best) { best = iou; bidx = a; }  // strict > keeps first index
    }
    __shared__ float sv[256];
    __shared__ int   si[256];
    int tid = threadIdx.x;
    sv[tid] = best; si[tid] = bidx;
    __syncthreads();
    for (int s = blockDim.x >> 1; s > 0; s >>= 1) {
        if (tid < s) {
            float ov = sv[tid + s]; int oi = si[tid + s];
            if (ov > sv[tid] || (ov == sv[tid] && oi < si[tid])) {
                sv[tid] = ov; si[tid] = oi;
            }
        }
        __syncthreads();
    }
    if (tid == 0)
        g_gtbest[n * P + p] = (sv[0] > 0.f) ? si[0] : -1;  // lowq = valid & gt_max>0
}

__device__ __forceinline__ float clipf(float x) {
    return fminf(fmaxf(x, EPSF), 1.0f - EPSF);
}

// Main per-anchor kernel: assignment + score/cls/bbox loss contributions.
__global__ void main_kernel(const float* __restrict__ y_true,
                            const float* __restrict__ bbox_true,
                            const float* __restrict__ conf_pred,
                            const float* __restrict__ logit_pred,
                            const float* __restrict__ bbox_pred,
                            const float4* __restrict__ anchors,
                            int N, int P, int A, int C) {
    int n = blockIdx.y;
    int tid = threadIdx.x;
    int a = blockIdx.x * blockDim.x + tid;

    __shared__ float4 s_gt[MAXP];
    __shared__ float  s_area[MAXP];
    __shared__ int    s_best[MAXP];
    __shared__ short  s_list[MAXP];
    __shared__ int    s_nv;

    if (tid < P) {
        float4 g = reinterpret_cast<const float4*>(bbox_true)[n * P + tid];
        s_gt[tid] = g;
        s_area[tid] = (g.z - g.x) * (g.w - g.y);
        s_best[tid] = g_gtbest[n * P + tid];
    }
    __syncthreads();
    if (tid == 0) {
        int nv = 0;
        for (int p = 0; p < P; p++) {
            float4 g = s_gt[p];
            if (g.x > 0.f || g.y > 0.f || g.z > 0.f || g.w > 0.f)
                s_list[nv++] = (short)p;
        }
        s_nv = nv;
    }
    __syncthreads();
    int nv = s_nv;

    float score = 0.f, cls = 0.f, bl = 0.f;
    int posc = 0;

    if (a < A) {
        float4 an = anchors[a];
        float areaa = (an.z - an.x) * (an.w - an.y);
        float maxiou = -1.0f;
        int tix = 0;
        #pragma unroll 4
        for (int i = 0; i < nv; i++) {
            int p = s_list[i];
            float4 g = s_gt[p];
            float iw = fmaxf(fminf(an.z, g.z) - fmaxf(an.x, g.x), 0.f);
            float ih = fmaxf(fminf(an.w, g.w) - fmaxf(an.y, g.y), 0.f);
            float inter = iw * ih;
            float iou = inter / (areaa + s_area[p] - inter + EPSF);
            if (iou > maxiou) { maxiou = iou; tix = p; }  // first-index argmax
        }
        bool pos = (maxiou >= POS_THR);
        bool neg = (maxiou < NEG_THR);
        // low-quality match override (last-wins over p, matching scatter order)
        for (int i = 0; i < nv; i++) {
            int p = s_list[i];
            if (s_best[p] == a) { pos = true; tix = p; }
        }
        neg = neg && !pos;

        // score loss (BCE on objectness), weight = (pos||neg)
        float pc = clipf(conf_pred[(size_t)n * A + a]);
        if (pos)      score = -logf(pc);
        else if (neg) score = -logf(1.0f - pc);

        if (pos) {
            posc = 1;
            // class focal loss (one-hot target)
            const float4* trow = reinterpret_cast<const float4*>(
                y_true + ((size_t)n * P + tix) * C);
            const float4* qrow = reinterpret_cast<const float4*>(
                logit_pred + ((size_t)n * A + a) * C);
            for (int c4 = 0; c4 < C / 4; c4++) {
                float4 tv = trow[c4];
                float4 qv = qrow[c4];
                float tt[4] = {tv.x, tv.y, tv.z, tv.w};
                float qq[4] = {qv.x, qv.y, qv.z, qv.w};
                #pragma unroll
                for (int j = 0; j < 4; j++) {
                    float t = tt[j];
                    float q = clipf(qq[j]);
                    float pt = t * q + (1.f - t) * (1.f - q);
                    float at = t * ALPHA_F + (1.f - t) * (1.f - ALPHA_F);
                    float om = 1.f - pt;
                    cls += -at * om * om * logf(pt);
                }
            }
            // CIoU loss
            float4 bt = s_gt[tix];
            float4 bp = reinterpret_cast<const float4*>(
                bbox_pred)[(size_t)n * A + a];
            float ix1 = fmaxf(bt.x, bp.x), iy1 = fmaxf(bt.y, bp.y);
            float ix2 = fminf(bt.z, bp.z), iy2 = fminf(bt.w, bp.w);
            float inter = fmaxf(ix2 - ix1, 0.f) * fmaxf(iy2 - iy1, 0.f);
            float wt = bt.z - bt.x, ht = bt.w - bt.y;
            float wp = bp.z - bp.x, hp = bp.w - bp.y;
            float uni = wt * ht + wp * hp - inter + EPSF;
            float iou = inter / uni;
            float cw = fmaxf(bt.z, bp.z) - fminf(bt.x, bp.x);
            float ch = fmaxf(bt.w, bp.w) - fminf(bt.y, bp.y);
            float c2 = cw * cw + ch * ch + EPSF;
            float dx = bt.x + bt.z - bp.x - bp.z;
            float dy = bt.y + bt.w - bp.y - bp.w;
            float rho2 = (dx * dx + dy * dy) * 0.25f;
            float dat = atanf(wt / (ht + EPSF)) - atanf(wp / (hp + EPSF));
            float v = (4.0f / (float)(M_PI * M_PI)) * dat * dat;
            float alpha = v / (1.0f - iou + v + EPSF);
            bl = 1.0f - iou + rho2 / c2 + alpha * v;
        }
    }

    // Block reduction: warp shuffle -> shared -> single atomic per block
    unsigned mask = 0xffffffffu;
    #pragma unroll
    for (int off = 16; off > 0; off >>= 1) {
        score += __shfl_down_sync(mask, score, off);
        cls   += __shfl_down_sync(mask, cls, off);
        bl    += __shfl_down_sync(mask, bl, off);
        posc  += __shfl_down_sync(mask, posc, off);
    }
    __shared__ float rs0[8], rs1[8], rs2[8];
    __shared__ int   ri[8];
    int lane = tid & 31, warp = tid >> 5;
    if (lane == 0) { rs0[warp] = score; rs1[warp] = cls; rs2[warp] = bl; ri[warp] = posc; }
    __syncthreads();
    if (tid == 0) {
        float t0 = 0.f, t1 = 0.f, t2 = 0.f; int tc = 0;
        int nw = blockDim.x >> 5;
        for (int w = 0; w < nw; w++) { t0 += rs0[w]; t1 += rs1[w]; t2 += rs2[w]; tc += ri[w]; }
        atomicAdd(&g_sums[0], (double)t0);
        atomicAdd(&g_sums[1], (double)t1);
        atomicAdd(&g_sums[2], (double)t2);
        if (tc) atomicAdd(&g_poscnt[n], tc);
    }
}

__global__ void finalize_kernel(float* __restrict__ out, int N) {
    if (threadIdx.x == 0) {
        double af = 0.0;
        for (int n = 0; n < N; n++) {
            int c = g_poscnt[n];
            af += (double)(c > 1 ? c : 1);
        }
        #pragma unroll
        for (int i = 0; i < 3; i++) {
            float v = (float)(g_sums[i] / af);
            if (isnan(v) || isinf(v)) v = 0.f;
            out[i] = v;
        }
    }
}

extern "C" void kernel_launch(void* const* d_in, const int* in_sizes, int n_in,
                              void* d_out, int out_size) {
    const float* y_true    = (const float*)d_in[0];
    const float* bbox_true = (const float*)d_in[1];
    const float* conf_pred = (const float*)d_in[2];
    const float* logit     = (const float*)d_in[3];
    const float* bbox_pred = (const float*)d_in[4];
    const float* anchors   = (const float*)d_in[5];

    int A = in_sizes[5] / 4;
    int N = in_sizes[2] / A;
    int C = in_sizes[3] / (N * A);
    int P = in_sizes[1] / (N * 4);

    init_kernel<<<1, 64>>>();
    gt_best_kernel<<<dim3(P, N), 256>>>(bbox_true, (const float4*)anchors, N, P, A);
    main_kernel<<<dim3((A + 255) / 256, N), 256>>>(
        y_true, bbox_true, conf_pred, logit, bbox_pred,
        (const float4*)anchors, N, P, A, C);
    finalize_kernel<<<1, 32>>>((float*)d_out, N);
}

// round 2
// speedup vs baseline: 1.9693x; 1.9693x over previous
#include <cuda_runtime.h>
#include <math.h>

#define EPSF 1e-7f
#define POS_THR 0.5f
#define NEG_THR 0.4f
#define ALPHA_F 0.25f

#define MAXN 32
#define MAXP 100
#define MAXA 25600

// Scratch (static device globals; no allocation allowed)
__device__ double        g_sumn[MAXN * 3];        // per-batch partial sums
__device__ int           g_poscnt[MAXN];          // per-batch positive counts
__device__ int           g_gtbest[MAXN * MAXP];   // best anchor per GT (lowq), else -1
__device__ unsigned char g_ovr[MAXN * MAXA];      // per-anchor lowq override: p+1 or 0

// ---------------------------------------------------------------------------
// Per-(GT,batch) best-anchor search, division-free argmax via cross-mult.
// ---------------------------------------------------------------------------
__global__ void gt_best_kernel(const float4* __restrict__ bbox_true,
                               const float4* __restrict__ anchors,
                               int N, int P, int A) {
    int p = blockIdx.x, n = blockIdx.y;
    const float4 g = bbox_true[n * P + p];
    bool valid = (g.x > 0.f) || (g.y > 0.f) || (g.z > 0.f) || (g.w > 0.f);
    if (!valid) {
        if (threadIdx.x == 0) g_gtbest[n * P + p] = -1;
        return;
    }
    float areab = (g.z - g.x) * (g.w - g.y);
    // best kept as (inter, denom, idx); iou = inter/denom, denom > 0
    float bi = -1.0f, bd = 1.0f;
    int bidx = 0x7fffffff;
    for (int a = threadIdx.x; a < A; a += blockDim.x) {
        float4 an = anchors[a];
        float iw = fmaxf(fminf(an.z, g.z) - fmaxf(an.x, g.x), 0.f);
        float ih = fmaxf(fminf(an.w, g.w) - fmaxf(an.y, g.y), 0.f);
        float inter = iw * ih;
        float areaa = (an.z - an.x) * (an.w - an.y);
        float denom = areaa + areab - inter + EPSF;
        // strict greater: inter/denom > bi/bd  <=>  inter*bd > bi*denom
        if (inter * bd > bi * denom) { bi = inter; bd = denom; bidx = a; }
    }
    __shared__ float sI[512], sD[512];
    __shared__ int   sX[512];
    int tid = threadIdx.x;
    sI[tid] = bi; sD[tid] = bd; sX[tid] = bidx;
    __syncthreads();
    for (int s = blockDim.x >> 1; s > 0; s >>= 1) {
        if (tid < s) {
            float oi = sI[tid + s], od = sD[tid + s]; int ox = sX[tid + s];
            float p1 = oi * sD[tid], p2 = sI[tid] * od;
            if (p1 > p2 || (p1 == p2 && ox < sX[tid])) {
                sI[tid] = oi; sD[tid] = od; sX[tid] = ox;
            }
        }
        __syncthreads();
    }
    if (tid == 0)
        g_gtbest[n * P + p] = (sI[0] > 0.f) ? sX[0] : -1;   // lowq = gt_max > 0
}

// ---------------------------------------------------------------------------
// Per-batch: zero accumulators + override slice, scatter lowq overrides
// (ascending p, single thread => last-wins, matching reference scatter order).
// ---------------------------------------------------------------------------
__global__ void ovr_scatter_kernel(int N, int P, int A) {
    int n = blockIdx.x;
    uint4* dst = reinterpret_cast<uint4*>(g_ovr + (size_t)n * A);
    int n16 = A / 16;
    const uint4 z = {0u, 0u, 0u, 0u};
    for (int i = threadIdx.x; i < n16; i += blockDim.x) dst[i] = z;
    for (int i = n16 * 16 + threadIdx.x; i < A; i += blockDim.x)
        g_ovr[(size_t)n * A + i] = 0;
    __syncthreads();
    if (threadIdx.x == 0) {
        g_poscnt[n] = 0;
        g_sumn[n * 3 + 0] = 0.0;
        g_sumn[n * 3 + 1] = 0.0;
        g_sumn[n * 3 + 2] = 0.0;
        for (int p = 0; p < P; p++) {
            int b = g_gtbest[n * P + p];
            if (b >= 0) g_ovr[(size_t)n * A + b] = (unsigned char)(p + 1);
        }
    }
}

__device__ __forceinline__ float clipf(float x) {
    return fminf(fmaxf(x, EPSF), 1.0f - EPSF);
}

// ---------------------------------------------------------------------------
// Main per-anchor kernel.
// ---------------------------------------------------------------------------
__global__ void main_kernel(const float* __restrict__ y_true,
                            const float4* __restrict__ bbox_true,
                            const float* __restrict__ conf_pred,
                            const float* __restrict__ logit_pred,
                            const float4* __restrict__ bbox_pred,
                            const float4* __restrict__ anchors,
                            int N, int P, int A, int C) {
    int n = blockIdx.y;
    int tid = threadIdx.x;
    int a = blockIdx.x * blockDim.x + tid;

    __shared__ float4 s_gt[MAXP];     // compacted, order-preserving
    __shared__ float  s_area[MAXP];
    __shared__ short  s_orig[MAXP];
    __shared__ float4 s_rawgt[MAXP];  // original indexing (for tix lookup)
    __shared__ int    s_wcnt[4];
    __shared__ int    s_nv;

    // Stable parallel compaction of valid GTs (P <= 128 assumed; P=100 here)
    {
        bool v = false; float4 g = {0,0,0,0};
        if (tid < P) {
            g = bbox_true[n * P + tid];
            s_rawgt[tid] = g;
            v = (g.x > 0.f) || (g.y > 0.f) || (g.z > 0.f) || (g.w > 0.f);
        }
        if (tid < 128) {
            unsigned m = __ballot_sync(0xffffffffu, v);
            int w = tid >> 5, lane = tid & 31;
            if (lane == 0) s_wcnt[w] = __popc(m);
            __syncthreads();
            if (tid == 0) s_nv = s_wcnt[0] + s_wcnt[1] + s_wcnt[2] + s_wcnt[3];
            int off = 0;
            for (int i = 0; i < w; i++) off += s_wcnt[i];
            if (v) {
                int pos = off + __popc(m & ((1u << lane) - 1u));
                s_gt[pos] = g;
                s_area[pos] = (g.z - g.x) * (g.w - g.y);
                s_orig[pos] = (short)tid;
            }
        } else {
            __syncthreads();
        }
        __syncthreads();
    }
    int nv = s_nv;

    float score = 0.f, cls = 0.f, bl = 0.f;
    int posc = 0;

    if (a < A) {
        float4 an = anchors[a];
        float areaa = (an.z - an.x) * (an.w - an.y);
        // division-free running argmax: value = bi/bd
        float bi = -1.0f, bd = 1.0f;
        int tixc = 0;
        #pragma unroll 2
        for (int i = 0; i < nv; i++) {
            float4 g = s_gt[i];
            float iw = fmaxf(fminf(an.z, g.z) - fmaxf(an.x, g.x), 0.f);
            float ih = fmaxf(fminf(an.w, g.w) - fmaxf(an.y, g.y), 0.f);
            float inter = iw * ih;
            float denom = areaa + s_area[i] - inter + EPSF;
            if (inter * bd > bi * denom) { bi = inter; bd = denom; tixc = i; }
        }
        float maxiou = (nv > 0) ? (bi / bd) : -1.0f;   // IEEE div once
        int tix = (nv > 0) ? (int)s_orig[tixc] : 0;

        bool pos = (maxiou >= POS_THR);
        bool neg = (maxiou < NEG_THR);
        unsigned char ov = g_ovr[(size_t)n * A + a];
        if (ov) { pos = true; tix = ov - 1; }
        neg = neg && !pos;

        float pc = clipf(conf_pred[(size_t)n * A + a]);
        if (pos)      score = -__logf(pc);
        else if (neg) score = -__logf(1.0f - pc);

        if (pos) {
            posc = 1;
            const float4* trow = reinterpret_cast<const float4*>(
                y_true + ((size_t)n * P + tix) * C);
            const float4* qrow = reinterpret_cast<const float4*>(
                logit_pred + ((size_t)n * A + a) * C);
            for (int c4 = 0; c4 < C / 4; c4++) {
                float4 tv = trow[c4];
                float4 qv = qrow[c4];
                float tt[4] = {tv.x, tv.y, tv.z, tv.w};
                float qq[4] = {qv.x, qv.y, qv.z, qv.w};
                #pragma unroll
                for (int j = 0; j < 4; j++) {
                    float t = tt[j];
                    float q = clipf(qq[j]);
                    float pt = t * q + (1.f - t) * (1.f - q);
                    float at = t * ALPHA_F + (1.f - t) * (1.f - ALPHA_F);
                    float om = 1.f - pt;
                    cls += -at * om * om * __logf(pt);
                }
            }
            float4 bt = s_rawgt[tix];
            float4 bp = bbox_pred[(size_t)n * A + a];
            float ix1 = fmaxf(bt.x, bp.x), iy1 = fmaxf(bt.y, bp.y);
            float ix2 = fminf(bt.z, bp.z), iy2 = fminf(bt.w, bp.w);
            float inter = fmaxf(ix2 - ix1, 0.f) * fmaxf(iy2 - iy1, 0.f);
            float wt = bt.z - bt.x, ht = bt.w - bt.y;
            float wp = bp.z - bp.x, hp = bp.w - bp.y;
            float uni = wt * ht + wp * hp - inter + EPSF;
            float iou = inter / uni;
            float cw = fmaxf(bt.z, bp.z) - fminf(bt.x, bp.x);
            float ch = fmaxf(bt.w, bp.w) - fminf(bt.y, bp.y);
            float c2 = cw * cw + ch * ch + EPSF;
            float dx = bt.x + bt.z - bp.x - bp.z;
            float dy = bt.y + bt.w - bp.y - bp.w;
            float rho2 = (dx * dx + dy * dy) * 0.25f;
            float dat = atanf(wt / (ht + EPSF)) - atanf(wp / (hp + EPSF));
            float v = (4.0f / (float)(M_PI * M_PI)) * dat * dat;
            float alpha = v / (1.0f - iou + v + EPSF);
            bl = 1.0f - iou + rho2 / c2 + alpha * v;
        }
    }

    // Block reduction -> one atomic per block per (n, component)
    unsigned mask = 0xffffffffu;
    #pragma unroll
    for (int off = 16; off > 0; off >>= 1) {
        score += __shfl_down_sync(mask, score, off);
        cls   += __shfl_down_sync(mask, cls, off);
        bl    += __shfl_down_sync(mask, bl, off);
        posc  += __shfl_down_sync(mask, posc, off);
    }
    __shared__ float rs0[8], rs1[8], rs2[8];
    __shared__ int   ri[8];
    int lane = tid & 31, warp = tid >> 5;
    if (lane == 0) { rs0[warp] = score; rs1[warp] = cls; rs2[warp] = bl; ri[warp] = posc; }
    __syncthreads();
    if (tid == 0) {
        float t0 = 0.f, t1 = 0.f, t2 = 0.f; int tc = 0;
        int nw = blockDim.x >> 5;
        for (int w = 0; w < nw; w++) { t0 += rs0[w]; t1 += rs1[w]; t2 += rs2[w]; tc += ri[w]; }
        atomicAdd(&g_sumn[n * 3 + 0], (double)t0);
        atomicAdd(&g_sumn[n * 3 + 1], (double)t1);
        atomicAdd(&g_sumn[n * 3 + 2], (double)t2);
        if (tc) atomicAdd(&g_poscnt[n], tc);
    }
}

__global__ void finalize_kernel(float* __restrict__ out, int N) {
    if (threadIdx.x == 0) {
        double af = 0.0, s0 = 0.0, s1 = 0.0, s2 = 0.0;
        for (int n = 0; n < N; n++) {
            int c = g_poscnt[n];
            af += (double)(c > 1 ? c : 1);
            s0 += g_sumn[n * 3 + 0];
            s1 += g_sumn[n * 3 + 1];
            s2 += g_sumn[n * 3 + 2];
        }
        double s[3] = {s0, s1, s2};
        #pragma unroll
        for (int i = 0; i < 3; i++) {
            float v = (float)(s[i] / af);
            if (isnan(v) || isinf(v)) v = 0.f;
            out[i] = v;
        }
    }
}

extern "C" void kernel_launch(void* const* d_in, const int* in_sizes, int n_in,
                              void* d_out, int out_size) {
    const float* y_true    = (const float*)d_in[0];
    const float* bbox_true = (const float*)d_in[1];
    const float* conf_pred = (const float*)d_in[2];
    const float* logit     = (const float*)d_in[3];
    const float* bbox_pred = (const float*)d_in[4];
    const float* anchors   = (const float*)d_in[5];

    int A = in_sizes[5] / 4;
    int N = in_sizes[2] / A;
    int C = in_sizes[3] / (N * A);
    int P = in_sizes[1] / (N * 4);

    gt_best_kernel<<<dim3(P, N), 512>>>(
        (const float4*)bbox_true, (const float4*)anchors, N, P, A);
    ovr_scatter_kernel<<<N, 256>>>(N, P, A);
    main_kernel<<<dim3((A + 255) / 256, N), 256>>>(
        y_true, (const float4*)bbox_true, conf_pred, logit,
        (const float4*)bbox_pred, (const float4*)anchors, N, P, A, C);
    finalize_kernel<<<1, 32>>>((float*)d_out, N);
}

// round 3
// speedup vs baseline: 2.6020x; 1.3212x over previous
#include <cuda_runtime.h>
#include <math.h>

#define EPSF 1e-7f
#define POS_THR 0.5f
#define NEG_THR 0.4f
#define ALPHA_F 0.25f

#define MAXN 32
#define MAXP 100
#define MAXA 25600

// Contiguous scratch so one memset clears everything that needs zeroing.
struct Scratch {
    unsigned long long gtkey[MAXN * MAXP]; // packed (iou_bits<<32)|~a per GT
    double             sumn[MAXN * 3];     // per-batch partial sums
    int                poscnt[MAXN];
    int                done;
};
__device__ Scratch g_s;
__device__ float2  g_amax[MAXN * MAXA];    // per-anchor {maxiou, int_as_float(tix)}

// ---------------------------------------------------------------------------
// Pass 1: fused per-anchor argmax + per-GT best-anchor (single IoU sweep).
// ---------------------------------------------------------------------------
__global__ void assign_kernel(const float4* __restrict__ bbox_true,
                              const float4* __restrict__ anchors,
                              int N, int P, int A) {
    int n = blockIdx.y;
    int tid = threadIdx.x;
    int a = blockIdx.x * blockDim.x + tid;

    __shared__ float4 s_gt[MAXP];
    __shared__ float  s_area[MAXP];
    __shared__ short  s_orig[MAXP];
    __shared__ unsigned long long s_key[MAXP];
    __shared__ int    s_wcnt[4];
    __shared__ int    s_nv;

    // Stable parallel compaction of valid GTs (P <= 128)
    {
        bool v = false; float4 g = {0,0,0,0};
        if (tid < P) {
            g = bbox_true[n * P + tid];
            v = (g.x > 0.f) || (g.y > 0.f) || (g.z > 0.f) || (g.w > 0.f);
            s_key[tid] = 0ull;
        }
        if (tid < 128) {
            unsigned m = __ballot_sync(0xffffffffu, v);
            int w = tid >> 5, lane = tid & 31;
            if (lane == 0) s_wcnt[w] = __popc(m);
            __syncthreads();
            if (tid == 0) s_nv = s_wcnt[0] + s_wcnt[1] + s_wcnt[2] + s_wcnt[3];
            int off = 0;
            for (int i = 0; i < w; i++) off += s_wcnt[i];
            if (v) {
                int pos = off + __popc(m & ((1u << lane) - 1u));
                s_gt[pos] = g;
                s_area[pos] = (g.z - g.x) * (g.w - g.y);
                s_orig[pos] = (short)tid;
            }
        } else {
            __syncthreads();
        }
        __syncthreads();
    }
    int nv = s_nv;

    if (a < A) {
        float4 an = anchors[a];
        float areaa = (an.z - an.x) * (an.w - an.y);
        float bi = -1.0f, bd = 1.0f;   // per-anchor best iou = bi/bd
        int tixc = 0;
        unsigned inv_a = ~(unsigned)a;
        #pragma unroll 2
        for (int i = 0; i < nv; i++) {
            float4 g = s_gt[i];
            float iw = fmaxf(fminf(an.z, g.z) - fmaxf(an.x, g.x), 0.f);
            float ih = fmaxf(fminf(an.w, g.w) - fmaxf(an.y, g.y), 0.f);
            float inter = iw * ih;
            float denom = areaa + s_area[i] - inter + EPSF;
            if (inter * bd > bi * denom) { bi = inter; bd = denom; tixc = i; }
            if (inter > 0.f) {
                // exact division only for overlapping pairs (~5%)
                float iou = inter / denom;
                unsigned long long key =
                    ((unsigned long long)__float_as_uint(iou) << 32) | inv_a;
                atomicMax(&s_key[i], key);
            }
        }
        float maxiou = (nv > 0) ? (bi / bd) : -1.0f;
        int tix = (nv > 0) ? (int)s_orig[tixc] : 0;
        float2 r; r.x = maxiou; r.y = __int_as_float(tix);
        g_amax[(size_t)n * A + a] = r;
    }
    __syncthreads();
    if (tid < nv && s_key[tid] != 0ull)
        atomicMax(&g_s.gtkey[n * P + (int)s_orig[tid]], s_key[tid]);
}

__device__ __forceinline__ float clipf(float x) {
    return fminf(fmaxf(x, EPSF), 1.0f - EPSF);
}

// ---------------------------------------------------------------------------
// Pass 2: per-anchor losses + fused finalize (last block writes output).
// ---------------------------------------------------------------------------
__global__ void loss_kernel(const float* __restrict__ y_true,
                            const float4* __restrict__ bbox_true,
                            const float* __restrict__ conf_pred,
                            const float* __restrict__ logit_pred,
                            const float4* __restrict__ bbox_pred,
                            float* __restrict__ out,
                            int N, int P, int A, int C, int totalBlocks) {
    int n = blockIdx.y;
    int tid = threadIdx.x;
    int a0 = blockIdx.x * blockDim.x;
    int a = a0 + tid;

    __shared__ float4 s_rawgt[MAXP];
    __shared__ int    s_ovr[256];   // lowq override: p+1 (max = last-wins), 0 none

    s_ovr[tid] = 0;
    if (tid < P) s_rawgt[tid] = bbox_true[n * P + tid];
    __syncthreads();
    if (tid < P) {
        unsigned long long key = g_s.gtkey[n * P + tid];
        if (key != 0ull) {
            int ba = (int)(~(unsigned)key);  // best anchor for this GT
            if (ba >= a0 && ba < a0 + 256) atomicMax(&s_ovr[ba - a0], tid + 1);
        }
    }
    __syncthreads();

    float score = 0.f, cls = 0.f, bl = 0.f;
    int posc = 0;

    if (a < A) {
        float2 am = g_amax[(size_t)n * A + a];
        float maxiou = am.x;
        int tix = __float_as_int(am.y);
        int ov = s_ovr[tid];
        bool pos = (maxiou >= POS_THR);
        bool neg = (maxiou < NEG_THR);
        if (ov) { pos = true; tix = ov - 1; }
        neg = neg && !pos;

        float pc = clipf(conf_pred[(size_t)n * A + a]);
        if (pos)      score = -__logf(pc);
        else if (neg) score = -__logf(1.0f - pc);

        if (pos) {
            posc = 1;
            const float4* trow = reinterpret_cast<const float4*>(
                y_true + ((size_t)n * P + tix) * C);
            const float4* qrow = reinterpret_cast<const float4*>(
                logit_pred + ((size_t)n * A + a) * C);
            for (int c4 = 0; c4 < C / 4; c4++) {
                float4 tv = trow[c4];
                float4 qv = qrow[c4];
                float tt[4] = {tv.x, tv.y, tv.z, tv.w};
                float qq[4] = {qv.x, qv.y, qv.z, qv.w};
                #pragma unroll
                for (int j = 0; j < 4; j++) {
                    float t = tt[j];
                    float q = clipf(qq[j]);
                    float pt = t * q + (1.f - t) * (1.f - q);
                    float at = t * ALPHA_F + (1.f - t) * (1.f - ALPHA_F);
                    float om = 1.f - pt;
                    cls += -at * om * om * __logf(pt);
                }
            }
            float4 bt = s_rawgt[tix];
            float4 bp = bbox_pred[(size_t)n * A + a];
            float ix1 = fmaxf(bt.x, bp.x), iy1 = fmaxf(bt.y, bp.y);
            float ix2 = fminf(bt.z, bp.z), iy2 = fminf(bt.w, bp.w);
            float inter = fmaxf(ix2 - ix1, 0.f) * fmaxf(iy2 - iy1, 0.f);
            float wt = bt.z - bt.x, ht = bt.w - bt.y;
            float wp = bp.z - bp.x, hp = bp.w - bp.y;
            float uni = wt * ht + wp * hp - inter + EPSF;
            float iou = inter / uni;
            float cw = fmaxf(bt.z, bp.z) - fminf(bt.x, bp.x);
            float ch = fmaxf(bt.w, bp.w) - fminf(bt.y, bp.y);
            float c2 = cw * cw + ch * ch + EPSF;
            float dx = bt.x + bt.z - bp.x - bp.z;
            float dy = bt.y + bt.w - bp.y - bp.w;
            float rho2 = (dx * dx + dy * dy) * 0.25f;
            float dat = atanf(wt / (ht + EPSF)) - atanf(wp / (hp + EPSF));
            float v = (4.0f / (float)(M_PI * M_PI)) * dat * dat;
            float alpha = v / (1.0f - iou + v + EPSF);
            bl = 1.0f - iou + rho2 / c2 + alpha * v;
        }
    }

    // Block reduction -> per-(n,component) atomics
    unsigned mask = 0xffffffffu;
    #pragma unroll
    for (int off = 16; off > 0; off >>= 1) {
        score += __shfl_down_sync(mask, score, off);
        cls   += __shfl_down_sync(mask, cls, off);
        bl    += __shfl_down_sync(mask, bl, off);
        posc  += __shfl_down_sync(mask, posc, off);
    }
    __shared__ float rs0[8], rs1[8], rs2[8];
    __shared__ int   ri[8];
    __shared__ bool  s_last;
    int lane = tid & 31, warp = tid >> 5;
    if (lane == 0) { rs0[warp] = score; rs1[warp] = cls; rs2[warp] = bl; ri[warp] = posc; }
    __syncthreads();
    if (tid == 0) {
        float t0 = 0.f, t1 = 0.f, t2 = 0.f; int tc = 0;
        for (int w = 0; w < 8; w++) { t0 += rs0[w]; t1 += rs1[w]; t2 += rs2[w]; tc += ri[w]; }
        atomicAdd(&g_s.sumn[n * 3 + 0], (double)t0);
        atomicAdd(&g_s.sumn[n * 3 + 1], (double)t1);
        atomicAdd(&g_s.sumn[n * 3 + 2], (double)t2);
        if (tc) atomicAdd(&g_s.poscnt[n], tc);
        __threadfence();
        int d = atomicAdd(&g_s.done, 1);
        s_last = (d == totalBlocks - 1);
    }
    __syncthreads();
    if (s_last && tid == 0) {
        __threadfence();
        double af = 0.0, s0 = 0.0, s1 = 0.0, s2 = 0.0;
        for (int nn = 0; nn < N; nn++) {
            int c = g_s.poscnt[nn];
            af += (double)(c > 1 ? c : 1);
            s0 += g_s.sumn[nn * 3 + 0];
            s1 += g_s.sumn[nn * 3 + 1];
            s2 += g_s.sumn[nn * 3 + 2];
        }
        double s[3] = {s0, s1, s2};
        #pragma unroll
        for (int i = 0; i < 3; i++) {
            float v = (float)(s[i] / af);
            if (isnan(v) || isinf(v)) v = 0.f;
            out[i] = v;
        }
    }
}

extern "C" void kernel_launch(void* const* d_in, const int* in_sizes, int n_in,
                              void* d_out, int out_size) {
    const float* y_true    = (const float*)d_in[0];
    const float* bbox_true = (const float*)d_in[1];
    const float* conf_pred = (const float*)d_in[2];
    const float* logit     = (const float*)d_in[3];
    const float* bbox_pred = (const float*)d_in[4];
    const float* anchors   = (const float*)d_in[5];

    int A = in_sizes[5] / 4;
    int N = in_sizes[2] / A;
    int C = in_sizes[3] / (N * A);
    int P = in_sizes[1] / (N * 4);

    void* scratch_addr = nullptr;
    cudaGetSymbolAddress(&scratch_addr, g_s);
    cudaMemsetAsync(scratch_addr, 0, sizeof(Scratch));

    int gx = (A + 255) / 256;
    assign_kernel<<<dim3(gx, N), 256>>>(
        (const float4*)bbox_true, (const float4*)anchors, N, P, A);
    loss_kernel<<<dim3(gx, N), 256>>>(
        y_true, (const float4*)bbox_true, conf_pred, logit,
        (const float4*)bbox_pred, (float*)d_out, N, P, A, C, gx * N);
}